// round 3
// baseline (speedup 1.0000x reference)
#include <cuda_runtime.h>

// SmartDoorClassifierv1 — fused CNN (LIF collapses: alpha = exp(-200) == 0 in fp32).
// Round 2: packed fp32x2 FFMA (full-rate fp32 path on sm_103a), halo-padded
// smem layouts (no bounds checks; patch pairs come directly from LDS.64).

#define THREADS 256
using u64 = unsigned long long;

__device__ __forceinline__ u64 pk(float lo, float hi) {
    u64 r;
    asm("mov.b64 %0, {%1, %2};" : "=l"(r) : "f"(lo), "f"(hi));
    return r;
}
__device__ __forceinline__ float2 up(u64 v) {
    float2 f;
    asm("mov.b64 {%0, %1}, %2;" : "=f"(f.x), "=f"(f.y) : "l"(v));
    return f;
}
__device__ __forceinline__ void fma2(u64& d, u64 a, u64 b) {
    asm("fma.rn.f32x2 %0, %1, %2, %0;" : "+l"(d) : "l"(a), "l"(b));
}

// dynamic smem layout (float indices)
//  p1p : 8 x 34 x 34                = 9248   (stage-1 pooled, 1-halo, zeroed)
//  p2p : 8 x 18 x 18                = 2592   (stage-2 pooled, 1-halo, zeroed)
//  p3  : 512                                 (flatten order)
//  dsw1: u64[64]   dup (w,w)        = 128 floats
//  dsw2: u64[576]  dup              = 1152
//  dsw3: u64[576]  dup              = 1152
//  red : 16
#define OFF_P1   0
#define OFF_P2   9248
#define OFF_P3   11840
#define OFF_W1   12352
#define OFF_W2   (12352 + 128)
#define OFF_W3   (12352 + 128 + 1152)
#define OFF_RED  (12352 + 128 + 1152 + 1152)
#define SMEM_FLOATS (OFF_RED + 16)

__global__ __launch_bounds__(THREADS)
void snn_fused_kernel(const float* __restrict__ x,
                      const float* __restrict__ w1,
                      const float* __restrict__ w2,
                      const float* __restrict__ w3,
                      const float* __restrict__ wfc,
                      float* __restrict__ out)
{
    extern __shared__ float smem[];
    float* p1p  = smem + OFF_P1;
    float* p2p  = smem + OFF_P2;
    float* p3   = smem + OFF_P3;
    u64*   dsw1 = (u64*)(smem + OFF_W1);
    u64*   dsw2 = (u64*)(smem + OFF_W2);
    u64*   dsw3 = (u64*)(smem + OFF_W3);
    float* red  = smem + OFF_RED;

    const int tid = threadIdx.x;
    const int n   = blockIdx.x;

    // ---- init: duplicated packed weights + zero-filled padded planes ----
    if (tid < 64) dsw1[tid] = pk(w1[tid], w1[tid]);
    for (int i = tid; i < 576; i += THREADS) {
        dsw2[i] = pk(w2[i], w2[i]);
        dsw3[i] = pk(w3[i], w3[i]);
    }
    for (int i = tid; i < 9248; i += THREADS) p1p[i] = 0.f;
    for (int i = tid; i < 2592; i += THREADS) p2p[i] = 0.f;
    __syncthreads();

    // ================= Stage 1: conv1(2x2,s2) + floor(relu) + pool2 =========
    // Pooled pos (py,px) <- disjoint 4x4 input patch. Pack the two pool-x
    // conv positions into f32x2 lanes: w[0] pairs cols (0,2), w[1] cols (1,3).
    const float* xb = x + (size_t)n * (2 * 128 * 128);
    #pragma unroll
    for (int it = 0; it < 4; it++) {
        int pos = tid + it * THREADS;          // 0..1023
        int py = pos >> 5, px = pos & 31;
        u64 pa[2][4], pb[2][4];
        #pragma unroll
        for (int ic = 0; ic < 2; ic++) {
            const float* src = xb + ic * 16384 + (4 * py) * 128 + 4 * px;
            #pragma unroll
            for (int r = 0; r < 4; r++) {
                float4 v = *reinterpret_cast<const float4*>(src + r * 128);
                pa[ic][r] = pk(v.x, v.z);
                pb[ic][r] = pk(v.y, v.w);
            }
        }
        #pragma unroll
        for (int oc = 0; oc < 8; oc++) {
            u64 a0 = 0ull, a1 = 0ull;          // dy = 0, 1 (packed over dx)
            #pragma unroll
            for (int ic = 0; ic < 2; ic++) {
                const u64* w = dsw1 + (oc * 2 + ic) * 4;
                u64 w0 = w[0], w1_ = w[1], w2_ = w[2], w3_ = w[3];
                fma2(a0, pa[ic][0], w0);  fma2(a0, pb[ic][0], w1_);
                fma2(a0, pa[ic][1], w2_); fma2(a0, pb[ic][1], w3_);
                fma2(a1, pa[ic][2], w0);  fma2(a1, pb[ic][2], w1_);
                fma2(a1, pa[ic][3], w2_); fma2(a1, pb[ic][3], w3_);
            }
            float2 f0 = up(a0), f1 = up(a1);
            float m = fmaxf(fmaxf(floorf(fmaxf(f0.x, 0.f)), floorf(fmaxf(f0.y, 0.f))),
                            fmaxf(floorf(fmaxf(f1.x, 0.f)), floorf(fmaxf(f1.y, 0.f))));
            p1p[oc * 1156 + (py + 1) * 34 + (px + 1)] = m;
        }
    }
    __syncthreads();

    // ================= Stage 2: conv2(3x3,p1) + floor(relu) + pool2 =========
    // One pooled (py,px) of 16x16 per thread. Packed over pool-x: pairs
    // (p[c],p[c+1]); pr[r][0], pr[r][2] are direct LDS.64, pr[r][1] one pack.
    {
        int py = tid >> 4, px = tid & 15;
        u64 acc[8][2];
        #pragma unroll
        for (int oc = 0; oc < 8; oc++) { acc[oc][0] = 0ull; acc[oc][1] = 0ull; }

        #pragma unroll
        for (int ic = 0; ic < 8; ic++) {
            const float* base = p1p + ic * 1156 + (2 * py) * 34 + 2 * px;
            u64 pr[4][3];
            #pragma unroll
            for (int r = 0; r < 4; r++) {
                u64 a = *reinterpret_cast<const u64*>(base + r * 34);
                u64 b = *reinterpret_cast<const u64*>(base + r * 34 + 2);
                float2 af = up(a), bf = up(b);
                pr[r][0] = a;
                pr[r][1] = pk(af.y, bf.x);
                pr[r][2] = b;
            }
            #pragma unroll
            for (int oc = 0; oc < 8; oc++) {
                const u64* w = dsw2 + (oc * 8 + ic) * 9;
                #pragma unroll
                for (int dy = 0; dy < 2; dy++) {
                    u64 a = acc[oc][dy];
                    #pragma unroll
                    for (int ky = 0; ky < 3; ky++)
                        #pragma unroll
                        for (int kx = 0; kx < 3; kx++)
                            fma2(a, pr[dy + ky][kx], w[ky * 3 + kx]);
                    acc[oc][dy] = a;
                }
            }
        }
        #pragma unroll
        for (int oc = 0; oc < 8; oc++) {
            float2 f0 = up(acc[oc][0]), f1 = up(acc[oc][1]);
            float m = fmaxf(fmaxf(floorf(fmaxf(f0.x, 0.f)), floorf(fmaxf(f0.y, 0.f))),
                            fmaxf(floorf(fmaxf(f1.x, 0.f)), floorf(fmaxf(f1.y, 0.f))));
            p2p[oc * 324 + (py + 1) * 18 + (px + 1)] = m;
        }
    }
    __syncthreads();

    // ================= Stage 3: conv3(3x3,p2) + floor(relu) + pool2 =========
    // 64 pooled positions; 4 threads/pos, 2 out-channels each. Packed over dx.
    {
        int pos = tid >> 2;                // 0..63
        int ocg = tid & 3;
        int py = pos >> 3, px = pos & 7;
        u64 acc[2][2];
        acc[0][0] = acc[0][1] = acc[1][0] = acc[1][1] = 0ull;

        #pragma unroll
        for (int ic = 0; ic < 8; ic++) {
            const float* base = p2p + ic * 324 + (2 * py) * 18 + 2 * px;
            u64 pr[4][3];
            #pragma unroll
            for (int r = 0; r < 4; r++) {
                u64 a = *reinterpret_cast<const u64*>(base + r * 18);
                u64 b = *reinterpret_cast<const u64*>(base + r * 18 + 2);
                float2 af = up(a), bf = up(b);
                pr[r][0] = a;
                pr[r][1] = pk(af.y, bf.x);
                pr[r][2] = b;
            }
            #pragma unroll
            for (int j = 0; j < 2; j++) {
                int oc = ocg * 2 + j;
                const u64* w = dsw3 + (oc * 8 + ic) * 9;
                #pragma unroll
                for (int dy = 0; dy < 2; dy++) {
                    u64 a = acc[j][dy];
                    #pragma unroll
                    for (int ky = 0; ky < 3; ky++)
                        #pragma unroll
                        for (int kx = 0; kx < 3; kx++)
                            fma2(a, pr[dy + ky][kx], w[ky * 3 + kx]);
                    acc[j][dy] = a;
                }
            }
        }
        #pragma unroll
        for (int j = 0; j < 2; j++) {
            int oc = ocg * 2 + j;
            float2 f0 = up(acc[j][0]), f1 = up(acc[j][1]);
            float m = fmaxf(fmaxf(floorf(fmaxf(f0.x, 0.f)), floorf(fmaxf(f0.y, 0.f))),
                            fmaxf(floorf(fmaxf(f1.x, 0.f)), floorf(fmaxf(f1.y, 0.f))));
            p3[oc * 64 + py * 8 + px] = m;     // flatten order c*64 + y*8 + x
        }
    }
    __syncthreads();

    // ================= Stage 4: fc (512 -> 2) ===============================
    {
        float a0 = 0.f, a1 = 0.f;
        #pragma unroll
        for (int k = 0; k < 2; k++) {
            int j = tid + k * THREADS;         // 0..511
            float v = p3[j];
            a0 = fmaf(v, wfc[j],       a0);
            a1 = fmaf(v, wfc[512 + j], a1);
        }
        #pragma unroll
        for (int off = 16; off > 0; off >>= 1) {
            a0 += __shfl_down_sync(0xffffffffu, a0, off);
            a1 += __shfl_down_sync(0xffffffffu, a1, off);
        }
        if ((tid & 31) == 0) {
            red[tid >> 5]     = a0;
            red[8 + (tid >> 5)] = a1;
        }
        __syncthreads();
        if (tid == 0) {
            float s0 = 0.f, s1 = 0.f;
            #pragma unroll
            for (int i = 0; i < 8; i++) { s0 += red[i]; s1 += red[8 + i]; }
            out[n * 2 + 0] = s0;
            out[n * 2 + 1] = s1;
        }
    }
}

extern "C" void kernel_launch(void* const* d_in, const int* in_sizes, int n_in,
                              void* d_out, int out_size)
{
    const float* x   = (const float*)d_in[0];
    const float* w1  = (const float*)d_in[1];
    const float* w2  = (const float*)d_in[2];
    const float* w3  = (const float*)d_in[3];
    const float* wfc = (const float*)d_in[4];
    int nsamples = in_sizes[0] / (2 * 128 * 128);   // 1024

    size_t smem_bytes = SMEM_FLOATS * sizeof(float);  // ~59.3 KB
    cudaFuncSetAttribute(snn_fused_kernel,
                         cudaFuncAttributeMaxDynamicSharedMemorySize,
                         (int)smem_bytes);
    snn_fused_kernel<<<nsamples, THREADS, smem_bytes>>>(x, w1, w2, w3, wfc,
                                                        (float*)d_out);
}

// round 5
// speedup vs baseline: 1.1680x; 1.1680x over previous
#include <cuda_runtime.h>

// SmartDoorClassifierv1 — fused CNN (LIF collapses: alpha = exp(-200) == 0 in fp32).
// Round 3: scalar FFMA (R2's packed-f32x2 asm regressed: 242 regs, occ 12.5%)
// + halo-padded zero-filled smem planes from R2 (no bounds checks, LDS.64 loads).

#define THREADS 256

// dynamic smem layout (float indices)
//  p1p : 8 x 34 x 34 = 9248   (stage-1 pooled, 1-halo, zeroed)
//  p2p : 8 x 18 x 18 = 2592   (stage-2 pooled, 1-halo, zeroed)
//  p3  : 512                  (flatten order)
//  sw1 : 64, sw2: 576, sw3: 576, red: 16
#define OFF_P1   0
#define OFF_P2   9248
#define OFF_P3   11840
#define OFF_W1   12352
#define OFF_W2   (OFF_W1 + 64)
#define OFF_W3   (OFF_W2 + 576)
#define OFF_RED  (OFF_W3 + 576)
#define SMEM_FLOATS (OFF_RED + 16)

__global__ __launch_bounds__(THREADS, 2)
void snn_fused_kernel(const float* __restrict__ x,
                      const float* __restrict__ w1,
                      const float* __restrict__ w2,
                      const float* __restrict__ w3,
                      const float* __restrict__ wfc,
                      float* __restrict__ out)
{
    extern __shared__ float smem[];
    float* p1p = smem + OFF_P1;
    float* p2p = smem + OFF_P2;
    float* p3  = smem + OFF_P3;
    float* sw1 = smem + OFF_W1;
    float* sw2 = smem + OFF_W2;
    float* sw3 = smem + OFF_W3;
    float* red = smem + OFF_RED;

    const int tid = threadIdx.x;
    const int n   = blockIdx.x;

    // ---- init: weights + zero-filled padded planes ----
    if (tid < 64) sw1[tid] = w1[tid];
    for (int i = tid; i < 576; i += THREADS) {
        sw2[i] = w2[i];
        sw3[i] = w3[i];
    }
    for (int i = tid; i < 9248; i += THREADS) p1p[i] = 0.f;
    for (int i = tid; i < 2592; i += THREADS) p2p[i] = 0.f;
    __syncthreads();

    // ================= Stage 1: conv1(2x2,s2) + floor(relu) + pool2 =========
    // Pooled pos (py,px) <- disjoint 4x4 input patch per channel.
    const float* xb = x + (size_t)n * (2 * 128 * 128);
    #pragma unroll
    for (int it = 0; it < 4; it++) {
        int pos = tid + it * THREADS;          // 0..1023
        int py = pos >> 5, px = pos & 31;
        float in[2][4][4];
        #pragma unroll
        for (int ic = 0; ic < 2; ic++) {
            const float* src = xb + ic * 16384 + (4 * py) * 128 + 4 * px;
            #pragma unroll
            for (int r = 0; r < 4; r++) {
                float4 v = *reinterpret_cast<const float4*>(src + r * 128);
                in[ic][r][0] = v.x; in[ic][r][1] = v.y;
                in[ic][r][2] = v.z; in[ic][r][3] = v.w;
            }
        }
        #pragma unroll
        for (int oc = 0; oc < 8; oc++) {
            float m = 0.f;
            #pragma unroll
            for (int dy = 0; dy < 2; dy++) {
                #pragma unroll
                for (int dx = 0; dx < 2; dx++) {
                    float acc = 0.f;
                    #pragma unroll
                    for (int ic = 0; ic < 2; ic++) {
                        const float* w = &sw1[(oc * 2 + ic) * 4];
                        acc = fmaf(in[ic][2*dy+0][2*dx+0], w[0], acc);
                        acc = fmaf(in[ic][2*dy+0][2*dx+1], w[1], acc);
                        acc = fmaf(in[ic][2*dy+1][2*dx+0], w[2], acc);
                        acc = fmaf(in[ic][2*dy+1][2*dx+1], w[3], acc);
                    }
                    m = fmaxf(m, floorf(fmaxf(acc, 0.f)));
                }
            }
            p1p[oc * 1156 + (py + 1) * 34 + (px + 1)] = m;
        }
    }
    __syncthreads();

    // ================= Stage 2: conv2(3x3,p1) + floor(relu) + pool2 =========
    // One pooled (py,px) of 16x16 per thread; padded plane -> unconditional
    // LDS.64 patch loads (addresses 8B-aligned: even offsets everywhere).
    {
        int py = tid >> 4, px = tid & 15;
        float acc[8][2][2];
        #pragma unroll
        for (int oc = 0; oc < 8; oc++)
            #pragma unroll
            for (int a = 0; a < 2; a++)
                #pragma unroll
                for (int b = 0; b < 2; b++) acc[oc][a][b] = 0.f;

        #pragma unroll
        for (int ic = 0; ic < 8; ic++) {
            const float* base = p1p + ic * 1156 + (2 * py) * 34 + 2 * px;
            float patch[4][4];
            #pragma unroll
            for (int r = 0; r < 4; r++) {
                float2 a = *reinterpret_cast<const float2*>(base + r * 34);
                float2 b = *reinterpret_cast<const float2*>(base + r * 34 + 2);
                patch[r][0] = a.x; patch[r][1] = a.y;
                patch[r][2] = b.x; patch[r][3] = b.y;
            }
            #pragma unroll
            for (int oc = 0; oc < 8; oc++) {
                const float* w = &sw2[(oc * 8 + ic) * 9];
                #pragma unroll
                for (int dy = 0; dy < 2; dy++) {
                    #pragma unroll
                    for (int dx = 0; dx < 2; dx++) {
                        float a = acc[oc][dy][dx];
                        #pragma unroll
                        for (int ky = 0; ky < 3; ky++)
                            #pragma unroll
                            for (int kx = 0; kx < 3; kx++)
                                a = fmaf(patch[dy+ky][dx+kx], w[ky*3+kx], a);
                        acc[oc][dy][dx] = a;
                    }
                }
            }
        }
        #pragma unroll
        for (int oc = 0; oc < 8; oc++) {
            float m = 0.f;
            #pragma unroll
            for (int dy = 0; dy < 2; dy++)
                #pragma unroll
                for (int dx = 0; dx < 2; dx++)
                    m = fmaxf(m, floorf(fmaxf(acc[oc][dy][dx], 0.f)));
            p2p[oc * 324 + (py + 1) * 18 + (px + 1)] = m;
        }
    }
    __syncthreads();

    // ================= Stage 3: conv3(3x3,p2) + floor(relu) + pool2 =========
    // 64 pooled positions; 4 threads/pos, 2 out-channels each.
    {
        int pos = tid >> 2;                // 0..63
        int ocg = tid & 3;
        int py = pos >> 3, px = pos & 7;
        float acc[2][2][2];
        #pragma unroll
        for (int j = 0; j < 2; j++)
            #pragma unroll
            for (int a = 0; a < 2; a++)
                #pragma unroll
                for (int b = 0; b < 2; b++) acc[j][a][b] = 0.f;

        #pragma unroll
        for (int ic = 0; ic < 8; ic++) {
            const float* base = p2p + ic * 324 + (2 * py) * 18 + 2 * px;
            float patch[4][4];
            #pragma unroll
            for (int r = 0; r < 4; r++) {
                float2 a = *reinterpret_cast<const float2*>(base + r * 18);
                float2 b = *reinterpret_cast<const float2*>(base + r * 18 + 2);
                patch[r][0] = a.x; patch[r][1] = a.y;
                patch[r][2] = b.x; patch[r][3] = b.y;
            }
            #pragma unroll
            for (int j = 0; j < 2; j++) {
                int oc = ocg * 2 + j;
                const float* w = &sw3[(oc * 8 + ic) * 9];
                #pragma unroll
                for (int dy = 0; dy < 2; dy++) {
                    #pragma unroll
                    for (int dx = 0; dx < 2; dx++) {
                        float a = acc[j][dy][dx];
                        #pragma unroll
                        for (int ky = 0; ky < 3; ky++)
                            #pragma unroll
                            for (int kx = 0; kx < 3; kx++)
                                a = fmaf(patch[dy+ky][dx+kx], w[ky*3+kx], a);
                        acc[j][dy][dx] = a;
                    }
                }
            }
        }
        #pragma unroll
        for (int j = 0; j < 2; j++) {
            int oc = ocg * 2 + j;
            float m = 0.f;
            #pragma unroll
            for (int dy = 0; dy < 2; dy++)
                #pragma unroll
                for (int dx = 0; dx < 2; dx++)
                    m = fmaxf(m, floorf(fmaxf(acc[j][dy][dx], 0.f)));
            p3[oc * 64 + py * 8 + px] = m;     // flatten order c*64 + y*8 + x
        }
    }
    __syncthreads();

    // ================= Stage 4: fc (512 -> 2) ===============================
    {
        float a0 = 0.f, a1 = 0.f;
        #pragma unroll
        for (int k = 0; k < 2; k++) {
            int j = tid + k * THREADS;         // 0..511
            float v = p3[j];
            a0 = fmaf(v, wfc[j],       a0);
            a1 = fmaf(v, wfc[512 + j], a1);
        }
        #pragma unroll
        for (int off = 16; off > 0; off >>= 1) {
            a0 += __shfl_down_sync(0xffffffffu, a0, off);
            a1 += __shfl_down_sync(0xffffffffu, a1, off);
        }
        if ((tid & 31) == 0) {
            red[tid >> 5]       = a0;
            red[8 + (tid >> 5)] = a1;
        }
        __syncthreads();
        if (tid == 0) {
            float s0 = 0.f, s1 = 0.f;
            #pragma unroll
            for (int i = 0; i < 8; i++) { s0 += red[i]; s1 += red[8 + i]; }
            out[n * 2 + 0] = s0;
            out[n * 2 + 1] = s1;
        }
    }
}

extern "C" void kernel_launch(void* const* d_in, const int* in_sizes, int n_in,
                              void* d_out, int out_size)
{
    const float* x   = (const float*)d_in[0];
    const float* w1  = (const float*)d_in[1];
    const float* w2  = (const float*)d_in[2];
    const float* w3  = (const float*)d_in[3];
    const float* wfc = (const float*)d_in[4];
    int nsamples = in_sizes[0] / (2 * 128 * 128);   // 1024

    size_t smem_bytes = SMEM_FLOATS * sizeof(float);  // ~54.3 KB
    cudaFuncSetAttribute(snn_fused_kernel,
                         cudaFuncAttributeMaxDynamicSharedMemorySize,
                         (int)smem_bytes);
    snn_fused_kernel<<<nsamples, THREADS, smem_bytes>>>(x, w1, w2, w3, wfc,
                                                        (float*)d_out);
}